// round 2
// baseline (speedup 1.0000x reference)
#include <cuda_runtime.h>
#include <cstdint>

// Problem constants
#define BB 512
#define SS 512
#define CC 32
#define DD 512
#define EE 8
#define EMBW 32

// Scratch (device globals — no allocation allowed)
__device__ float g_wmix[SS * DD];     // mixed expert weights [S, D]
__device__ float g_colsum[DD];        // sum_s g_wmix[s, d]
__device__ float g_med[BB * CC];      // medians [B, C]
__device__ float g_gw[2];             // gate weights g1, g2
__device__ int   g_ge[2];             // selected experts e1, e2

// ---------------------------------------------------------------------------
// K0: gate.  logits separable => gates identical across batch.
// t_e = emb[e] . Wg[D:D+EMB]; top-2 + softmax.
// ---------------------------------------------------------------------------
__global__ void gate_kernel(const float* __restrict__ emb,
                            const float* __restrict__ Wg) {
    int lane = threadIdx.x;
    float t = -1e30f;
    if (lane < EE) {
        float s = 0.f;
        #pragma unroll
        for (int j = 0; j < EMBW; j++) s += emb[lane * EMBW + j] * Wg[DD + j];
        t = s;
    }
    float best = -1e30f, second = -1e30f;
    int be = 0, se = 0;
    #pragma unroll
    for (int e = 0; e < EE; e++) {
        float te = __shfl_sync(0xFFFFFFFFu, t, e);
        if (te > best)        { second = best; se = be; best = te; be = e; }
        else if (te > second) { second = te; se = e; }
    }
    if (lane == 0) {
        float e2 = expf(second - best);
        float inv = 1.0f / (1.0f + e2);
        g_gw[0] = inv;        // weight for best expert
        g_gw[1] = e2 * inv;   // weight for second expert
        g_ge[0] = be;
        g_ge[1] = se;
    }
}

// ---------------------------------------------------------------------------
// K1: Wmix = g1 * We[e1] + g2 * We[e2]   (262144 floats)
// ---------------------------------------------------------------------------
__global__ void wmix_kernel(const float* __restrict__ We) {
    int i = (blockIdx.x * blockDim.x + threadIdx.x) * 4;
    float g1 = g_gw[0], g2 = g_gw[1];
    const float* a = We + (size_t)g_ge[0] * SS * DD + i;
    const float* b = We + (size_t)g_ge[1] * SS * DD + i;
    float4 va = *(const float4*)a;
    float4 vb = *(const float4*)b;
    float4 r;
    r.x = g1 * va.x + g2 * vb.x;
    r.y = g1 * va.y + g2 * vb.y;
    r.z = g1 * va.z + g2 * vb.z;
    r.w = g1 * va.w + g2 * vb.w;
    *(float4*)(g_wmix + i) = r;
}

// ---------------------------------------------------------------------------
// K2: colsum[d] = sum_s Wmix[s, d]
// ---------------------------------------------------------------------------
__global__ void colsum_kernel() {
    int d = blockIdx.x * blockDim.x + threadIdx.x;
    float s = 0.f;
    for (int ss = 0; ss < SS; ss++) s += g_wmix[ss * DD + d];
    g_colsum[d] = s;
}

// ---------------------------------------------------------------------------
// K3: exact median over seq dim per (b, c).
// Block = (b, half-of-channels): 512 threads / 16 warps, 1 warp per channel.
// Stage x[b,:,16ch] into smem (transposed, stride 513 -> conflict-free),
// then per-warp MSB radix select over 16 regs/lane for order stats 255 & 256.
// ---------------------------------------------------------------------------
__device__ __forceinline__ unsigned f2ord(float f) {
    unsigned raw = __float_as_uint(f);
    return (raw & 0x80000000u) ? ~raw : (raw | 0x80000000u);
}
__device__ __forceinline__ float ord2f(unsigned u) {
    return (u & 0x80000000u) ? __uint_as_float(u ^ 0x80000000u)
                             : __uint_as_float(~u);
}

__global__ void __launch_bounds__(512) median_kernel(const float* __restrict__ x) {
    __shared__ float sm[16 * 513];
    int b = blockIdx.x >> 1;
    int half = blockIdx.x & 1;
    const float* xb = x + (size_t)b * SS * CC + half * 16;

    for (int i = threadIdx.x; i < 512 * 16; i += 512) {
        int s = i >> 4;
        int c = i & 15;
        sm[c * 513 + s] = xb[s * CC + c];
    }
    __syncthreads();

    int w = threadIdx.x >> 5;
    int lane = threadIdx.x & 31;

    unsigned u[16];
    #pragma unroll
    for (int r = 0; r < 16; r++)
        u[r] = f2ord(sm[w * 513 + lane + 32 * r]);

    // select 0-indexed order stat 255 (256th smallest)
    unsigned active = 0xFFFFu;
    int k = 255;
    for (int bit = 31; bit >= 0; bit--) {
        unsigned m0 = 0;
        #pragma unroll
        for (int r = 0; r < 16; r++)
            m0 |= ((((u[r] >> bit) & 1u) ^ 1u) << r);
        m0 &= active;
        int tot0 = __reduce_add_sync(0xFFFFFFFFu, __popc(m0));
        if (k < tot0) {
            active = m0;
        } else {
            k -= tot0;
            active &= ~m0;
        }
        int na = __reduce_add_sync(0xFFFFFFFFu, __popc(active));
        if (na == 1) break;   // warp-uniform
    }
    unsigned cand = 0;
    #pragma unroll
    for (int r = 0; r < 16; r++)
        if ((active >> r) & 1u) cand = u[r];
    unsigned v1 = __reduce_max_sync(0xFFFFFFFFu, cand);

    // order stat 256: if count(<= v1) >= 257 it's v1 again, else min of > v1
    int le = 0;
    unsigned gtmin = 0xFFFFFFFFu;
    #pragma unroll
    for (int r = 0; r < 16; r++) {
        le += (u[r] <= v1) ? 1 : 0;
        if (u[r] > v1 && u[r] < gtmin) gtmin = u[r];
    }
    int totle = __reduce_add_sync(0xFFFFFFFFu, le);
    unsigned mn = __reduce_min_sync(0xFFFFFFFFu, gtmin);
    unsigned v2 = (totle >= 257) ? v1 : mn;

    if (lane == 0)
        g_med[b * CC + half * 16 + w] = 0.5f * (ord2f(v1) + ord2f(v2));
}

// ---------------------------------------------------------------------------
// K4: main GEMM.  out[b,d,v] = sum_s Wmix[s,d] * x[b,s,v] - med[b,v]*colsum[d]
// CTA tile: one b, 128 d, all 32 v.  K chunks of 32, cp.async double buffer.
// 128 threads, each computes 8d x 4v.
// ---------------------------------------------------------------------------
#define DT 128
#define KC 32

__device__ __forceinline__ void cp_async16(void* dst, const void* src) {
    unsigned sm = (unsigned)__cvta_generic_to_shared(dst);
    asm volatile("cp.async.cg.shared.global [%0], [%1], 16;" :: "r"(sm), "l"(src));
}

__global__ void __launch_bounds__(128) gemm_kernel(const float* __restrict__ x,
                                                   float* __restrict__ out) {
    __shared__ float Ws[2][KC][DT];
    __shared__ float Xs[2][KC][CC];

    int b  = blockIdx.x >> 2;
    int d0 = (blockIdx.x & 3) * DT;
    int tid = threadIdx.x;
    int tv = tid & 7;    // 8 groups x 4 v
    int td = tid >> 3;   // 16 groups x 8 d
    const float* xb = x + (size_t)b * SS * CC;

    float acc[8][4];
    #pragma unroll
    for (int i = 0; i < 8; i++)
        #pragma unroll
        for (int j = 0; j < 4; j++) acc[i][j] = 0.f;

    // chunk loaders
    auto load_chunk = [&](int buf, int s0) {
        #pragma unroll
        for (int t = 0; t < 8; t++) {             // 1024 float4 of W
            int idx = tid + t * 128;
            int row = idx >> 5;
            int c4  = idx & 31;
            cp_async16(&Ws[buf][row][c4 * 4],
                       g_wmix + (size_t)(s0 + row) * DD + d0 + c4 * 4);
        }
        #pragma unroll
        for (int t = 0; t < 2; t++) {             // 256 float4 of x
            int idx = tid + t * 128;
            int row = idx >> 3;
            int c4  = idx & 7;
            cp_async16(&Xs[buf][row][c4 * 4],
                       xb + (size_t)(s0 + row) * CC + c4 * 4);
        }
        asm volatile("cp.async.commit_group;" ::: "memory");
    };

    load_chunk(0, 0);

    const int NCH = SS / KC;   // 16
    for (int ch = 0; ch < NCH; ch++) {
        asm volatile("cp.async.wait_group 0;" ::: "memory");
        __syncthreads();
        if (ch + 1 < NCH) load_chunk((ch + 1) & 1, (ch + 1) * KC);

        const float* wsp = &Ws[ch & 1][0][0];
        const float* xsp = &Xs[ch & 1][0][0];
        #pragma unroll
        for (int kk = 0; kk < KC; kk++) {
            float wr[8], xr[4];
            *(float4*)&wr[0] = *(const float4*)(wsp + kk * DT + td * 8);
            *(float4*)&wr[4] = *(const float4*)(wsp + kk * DT + td * 8 + 4);
            *(float4*)&xr[0] = *(const float4*)(xsp + kk * CC + tv * 4);
            #pragma unroll
            for (int i = 0; i < 8; i++)
                #pragma unroll
                for (int j = 0; j < 4; j++)
                    acc[i][j] = fmaf(wr[i], xr[j], acc[i][j]);
        }
        __syncthreads();
    }

    // epilogue: subtract med[b,v] * colsum[d]
    float4 md = *(const float4*)(g_med + b * CC + tv * 4);
    float mdv[4] = {md.x, md.y, md.z, md.w};
    #pragma unroll
    for (int i = 0; i < 8; i++) {
        float cs = g_colsum[d0 + td * 8 + i];
        float4 o;
        o.x = acc[i][0] - mdv[0] * cs;
        o.y = acc[i][1] - mdv[1] * cs;
        o.z = acc[i][2] - mdv[2] * cs;
        o.w = acc[i][3] - mdv[3] * cs;
        *(float4*)(out + (size_t)b * DD * CC + (size_t)(d0 + td * 8 + i) * CC
                   + tv * 4) = o;
    }
}

// ---------------------------------------------------------------------------
// Launch.  Inputs (metadata order): x, Wp, bp, emb, Wg, bg, We, k
// Wp/bp/bg/k are provably unused (gate separability).
// ---------------------------------------------------------------------------
extern "C" void kernel_launch(void* const* d_in, const int* in_sizes, int n_in,
                              void* d_out, int out_size) {
    const float* x   = (const float*)d_in[0];
    const float* emb = (const float*)d_in[3];
    const float* Wg  = (const float*)d_in[4];
    const float* We  = (const float*)d_in[6];
    float* out = (float*)d_out;

    gate_kernel<<<1, 32>>>(emb, Wg);
    wmix_kernel<<<256, 256>>>(We);
    colsum_kernel<<<2, 256>>>();
    median_kernel<<<BB * 2, 512>>>(x);
    gemm_kernel<<<BB * 4, 128>>>(x, out);
}

// round 4
// speedup vs baseline: 1.7032x; 1.7032x over previous
#include <cuda_runtime.h>
#include <cuda_bf16.h>
#include <cstdint>

// Problem constants
#define BB 512
#define SS 512
#define CC 32
#define DD 512
#define EE 8
#define EMBW 32

// ---------------------------------------------------------------------------
// Scratch (device globals — no allocation allowed)
// ---------------------------------------------------------------------------
__device__ __nv_bfloat16 g_Ahi[DD * SS];        // Wmix^T hi  [d][s] K-major
__device__ __nv_bfloat16 g_Alo[DD * SS];        // Wmix^T lo
__device__ __nv_bfloat16 g_Xhi[BB * CC * SS];   // xn hi [n=(b,v)][s] K-major
__device__ __nv_bfloat16 g_Xlo[BB * CC * SS];   // xn lo
__device__ float g_gw[2];
__device__ int   g_ge[2];

// ---------------------------------------------------------------------------
// helpers
// ---------------------------------------------------------------------------
__device__ __forceinline__ uint32_t smem_u32(const void* p) {
    uint32_t a;
    asm("{ .reg .u64 t; cvta.to.shared.u64 t, %1; cvt.u32.u64 %0, t; }"
        : "=r"(a) : "l"(p));
    return a;
}
__device__ __forceinline__ void cp_async16(uint32_t dst_smem, const void* src) {
    asm volatile("cp.async.cg.shared.global [%0], [%1], 16;"
                 :: "r"(dst_smem), "l"(src));
}
__device__ __forceinline__ void ldsm4(uint32_t* r, uint32_t addr) {
    asm volatile("ldmatrix.sync.aligned.m8n8.x4.shared.b16 {%0,%1,%2,%3}, [%4];"
                 : "=r"(r[0]), "=r"(r[1]), "=r"(r[2]), "=r"(r[3]) : "r"(addr));
}
__device__ __forceinline__ void mma_bf16(float* d, const uint32_t* a,
                                         uint32_t b0, uint32_t b1) {
    asm volatile(
        "mma.sync.aligned.m16n8k16.row.col.f32.bf16.bf16.f32 "
        "{%0,%1,%2,%3}, {%4,%5,%6,%7}, {%8,%9}, {%0,%1,%2,%3};"
        : "+f"(d[0]), "+f"(d[1]), "+f"(d[2]), "+f"(d[3])
        : "r"(a[0]), "r"(a[1]), "r"(a[2]), "r"(a[3]), "r"(b0), "r"(b1));
}

// ---------------------------------------------------------------------------
// K0: gate — logits separable => gates identical across batch.
// ---------------------------------------------------------------------------
__global__ void gate_kernel(const float* __restrict__ emb,
                            const float* __restrict__ Wg) {
    int lane = threadIdx.x;
    float t = -1e30f;
    if (lane < EE) {
        float s = 0.f;
        #pragma unroll
        for (int j = 0; j < EMBW; j++) s += emb[lane * EMBW + j] * Wg[DD + j];
        t = s;
    }
    float best = -1e30f, second = -1e30f;
    int be = 0, se = 0;
    #pragma unroll
    for (int e = 0; e < EE; e++) {
        float te = __shfl_sync(0xFFFFFFFFu, t, e);
        if (te > best)        { second = best; se = be; best = te; be = e; }
        else if (te > second) { second = te; se = e; }
    }
    if (lane == 0) {
        float e2 = expf(second - best);
        float inv = 1.0f / (1.0f + e2);
        g_gw[0] = inv;
        g_gw[1] = e2 * inv;
        g_ge[0] = be;
        g_ge[1] = se;
    }
}

// ---------------------------------------------------------------------------
// K1: prep_w — A[d][s] = g1*We[e1][s][d] + g2*We[e2][s][d], bf16 hi/lo split,
// K-major (s contiguous). 32x32 smem transpose tiles.
// ---------------------------------------------------------------------------
__global__ void prep_w(const float* __restrict__ We) {
    __shared__ float tile[32][33];
    int s0 = blockIdx.x * 32, d0 = blockIdx.y * 32;
    float g1 = g_gw[0], g2 = g_gw[1];
    const float* A1 = We + (size_t)g_ge[0] * SS * DD;
    const float* A2 = We + (size_t)g_ge[1] * SS * DD;
    int tx = threadIdx.x, ty = threadIdx.y;   // 32 x 8
    #pragma unroll
    for (int i = 0; i < 4; i++) {
        int s = s0 + ty + i * 8;
        tile[ty + i * 8][tx] =
            g1 * A1[(size_t)s * DD + d0 + tx] + g2 * A2[(size_t)s * DD + d0 + tx];
    }
    __syncthreads();
    #pragma unroll
    for (int i = 0; i < 4; i++) {
        int d = d0 + ty + i * 8;
        float v = tile[tx][ty + i * 8];
        __nv_bfloat16 h = __float2bfloat16(v);
        __nv_bfloat16 l = __float2bfloat16(v - __bfloat162float(h));
        g_Ahi[(size_t)d * SS + s0 + tx] = h;
        g_Alo[(size_t)d * SS + s0 + tx] = l;
    }
}

// ---------------------------------------------------------------------------
// K2: prep_x — fused exact median (per b,c over seq), subtract, bf16 hi/lo
// split, transposed K-major write.  Block = (b, half of 32 channels),
// 512 threads = 16 warps, 1 warp per channel.
// ---------------------------------------------------------------------------
__device__ __forceinline__ unsigned f2ord(float f) {
    unsigned raw = __float_as_uint(f);
    return (raw & 0x80000000u) ? ~raw : (raw | 0x80000000u);
}
__device__ __forceinline__ float ord2f(unsigned u) {
    return (u & 0x80000000u) ? __uint_as_float(u ^ 0x80000000u)
                             : __uint_as_float(~u);
}

__global__ void __launch_bounds__(512) prep_x(const float* __restrict__ x) {
    __shared__ float sm[16 * 513];
    int b = blockIdx.x >> 1;
    int half = blockIdx.x & 1;
    const float4* xb4 = (const float4*)(x + (size_t)b * SS * CC + half * 16);

    for (int i = threadIdx.x; i < 512 * 4; i += 512) {
        int s = i >> 2, q = i & 3;
        float4 v = xb4[s * 8 + q];
        sm[(q * 4 + 0) * 513 + s] = v.x;
        sm[(q * 4 + 1) * 513 + s] = v.y;
        sm[(q * 4 + 2) * 513 + s] = v.z;
        sm[(q * 4 + 3) * 513 + s] = v.w;
    }
    __syncthreads();

    int w = threadIdx.x >> 5;
    int lane = threadIdx.x & 31;

    unsigned u[16];
    #pragma unroll
    for (int r = 0; r < 16; r++)
        u[r] = f2ord(sm[w * 513 + lane + 32 * r]);

    // radix select: order stat 255
    unsigned active = 0xFFFFu;
    int k = 255, na = 512;
    for (int bit = 31; bit >= 0; bit--) {
        unsigned m0 = 0;
        #pragma unroll
        for (int r = 0; r < 16; r++)
            m0 |= ((((u[r] >> bit) & 1u) ^ 1u) << r);
        m0 &= active;
        int tot0 = __reduce_add_sync(0xFFFFFFFFu, __popc(m0));
        if (k < tot0) { active = m0; na = tot0; }
        else          { k -= tot0; active &= ~m0; na -= tot0; }
        if (na == 1) break;
    }
    unsigned cand = 0;
    #pragma unroll
    for (int r = 0; r < 16; r++)
        if ((active >> r) & 1u) cand = u[r];
    unsigned v1 = __reduce_max_sync(0xFFFFFFFFu, cand);

    // order stat 256
    int le = 0;
    unsigned gtmin = 0xFFFFFFFFu;
    #pragma unroll
    for (int r = 0; r < 16; r++) {
        le += (u[r] <= v1) ? 1 : 0;
        if (u[r] > v1 && u[r] < gtmin) gtmin = u[r];
    }
    int totle = __reduce_add_sync(0xFFFFFFFFu, le);
    unsigned mn = __reduce_min_sync(0xFFFFFFFFu, gtmin);
    unsigned v2 = (totle >= 257) ? v1 : mn;
    float med = 0.5f * (ord2f(v1) + ord2f(v2));

    int c = half * 16 + w;
    __nv_bfloat16* dsth = g_Xhi + (size_t)(b * CC + c) * SS;
    __nv_bfloat16* dstl = g_Xlo + (size_t)(b * CC + c) * SS;
    #pragma unroll
    for (int r = 0; r < 8; r++) {
        int s = r * 64 + lane * 2;
        float a0 = sm[w * 513 + s]     - med;
        float a1 = sm[w * 513 + s + 1] - med;
        __nv_bfloat16 h0 = __float2bfloat16(a0);
        __nv_bfloat16 h1 = __float2bfloat16(a1);
        __nv_bfloat16 l0 = __float2bfloat16(a0 - __bfloat162float(h0));
        __nv_bfloat16 l1 = __float2bfloat16(a1 - __bfloat162float(h1));
        *reinterpret_cast<__nv_bfloat162*>(dsth + s) = __halves2bfloat162(h0, h1);
        *reinterpret_cast<__nv_bfloat162*>(dstl + s) = __halves2bfloat162(l0, l1);
    }
}

// ---------------------------------------------------------------------------
// K3: mma.sync bf16x3 GEMM.  D[m=d, n=(b,v)] = sum_s A[d,s]*B[n,s],
// fp32 register accum.  CTA 128x128, 16 warps (warp tile 32x32), KC=64,
// SW128 swizzled smem, ldmatrix operands, double-buffered cp.async.
// ---------------------------------------------------------------------------
#define CTA_M 128
#define CTA_N 128
#define KC 64
#define NCH (SS / KC)        // 8
#define STG_BYTES 65536      // per stage: Ah 16K | Al 16K | Bh 16K | Bl 16K
#define OFF_AH 0
#define OFF_AL 16384
#define OFF_BH 32768
#define OFF_BL 49152
#define GSMEM (2 * STG_BYTES)

__global__ void __launch_bounds__(512) gemm_kernel(float* __restrict__ out) {
    extern __shared__ char smem[];
    uint32_t sb = smem_u32(smem);
    int tid = threadIdx.x;
    int lane = tid & 31, wid = tid >> 5;
    int wm = wid & 3, wn = wid >> 2;
    int m0 = (blockIdx.x & 3) * CTA_M;
    int n0 = (blockIdx.x >> 2) * CTA_N;

    const char* gAh = (const char*)(g_Ahi + (size_t)m0 * SS);
    const char* gAl = (const char*)(g_Alo + (size_t)m0 * SS);
    const char* gBh = (const char*)(g_Xhi + (size_t)n0 * SS);
    const char* gBl = (const char*)(g_Xlo + (size_t)n0 * SS);

    float acc[2][4][4];
    #pragma unroll
    for (int i = 0; i < 2; i++)
        #pragma unroll
        for (int j = 0; j < 4; j++)
            #pragma unroll
            for (int q = 0; q < 4; q++) acc[i][j][q] = 0.f;

    auto ldchunk = [&](int buf, int ch) {
        uint32_t tb = sb + buf * STG_BYTES;
        size_t kb = (size_t)ch * (KC * 2);   // byte offset along k
        #pragma unroll
        for (int t = 0; t < 2; t++) {
            int idx = tid + t * 512;
            int r = idx >> 3, c = idx & 7;
            uint32_t so = (uint32_t)(r * 128 + ((c * 16) ^ ((r & 7) << 4)));
            size_t go = (size_t)r * (SS * 2) + kb + c * 16;
            cp_async16(tb + OFF_AH + so, gAh + go);
            cp_async16(tb + OFF_AL + so, gAl + go);
            cp_async16(tb + OFF_BH + so, gBh + go);
            cp_async16(tb + OFF_BL + so, gBl + go);
        }
        asm volatile("cp.async.commit_group;" ::: "memory");
    };

    ldchunk(0, 0);

    int r8 = lane & 7;
    int half8 = ((lane >> 3) & 1) * 8;
    int kh16 = (lane >> 4) * 16;

    for (int ch = 0; ch < NCH; ch++) {
        if (ch + 1 < NCH) {
            ldchunk((ch + 1) & 1, ch + 1);
            asm volatile("cp.async.wait_group 1;" ::: "memory");
        } else {
            asm volatile("cp.async.wait_group 0;" ::: "memory");
        }
        __syncthreads();

        uint32_t tb = sb + (ch & 1) * STG_BYTES;
        #pragma unroll
        for (int ks = 0; ks < 4; ks++) {
            int kb0 = ks * 32 + kh16;
            uint32_t aH[2][4], aL[2][4], bH[2][4], bL[2][4];
            #pragma unroll
            for (int mb = 0; mb < 2; mb++) {
                int row = wm * 32 + mb * 16 + half8 + r8;
                uint32_t ad = (uint32_t)(row * 128 + (kb0 ^ ((row & 7) << 4)));
                ldsm4(aH[mb], tb + OFF_AH + ad);
                ldsm4(aL[mb], tb + OFF_AL + ad);
            }
            #pragma unroll
            for (int nb2 = 0; nb2 < 2; nb2++) {
                int row = wn * 32 + nb2 * 16 + half8 + r8;
                uint32_t ad = (uint32_t)(row * 128 + (kb0 ^ ((row & 7) << 4)));
                ldsm4(bH[nb2], tb + OFF_BH + ad);
                ldsm4(bL[nb2], tb + OFF_BL + ad);
            }
            #pragma unroll
            for (int mb = 0; mb < 2; mb++)
                #pragma unroll
                for (int nb2 = 0; nb2 < 2; nb2++)
                    #pragma unroll
                    for (int s = 0; s < 2; s++) {
                        float* d = acc[mb][nb2 * 2 + s];
                        mma_bf16(d, aH[mb], bH[nb2][s], bH[nb2][s + 2]);
                        mma_bf16(d, aH[mb], bL[nb2][s], bL[nb2][s + 2]);
                        mma_bf16(d, aL[mb], bH[nb2][s], bH[nb2][s + 2]);
                    }
        }
        __syncthreads();
    }

    // epilogue: warp's 32 n-columns are exactly one batch row b
    int bidx = (n0 >> 5) + wn;
    float* ob = out + (size_t)bidx * DD * CC;
    #pragma unroll
    for (int mb = 0; mb < 2; mb++) {
        int dr = m0 + wm * 32 + mb * 16 + (lane >> 2);
        #pragma unroll
        for (int nb = 0; nb < 4; nb++) {
            int v = nb * 8 + 2 * (lane & 3);
            *(float2*)(ob + (size_t)dr * CC + v) =
                make_float2(acc[mb][nb][0], acc[mb][nb][1]);
            *(float2*)(ob + (size_t)(dr + 8) * CC + v) =
                make_float2(acc[mb][nb][2], acc[mb][nb][3]);
        }
    }
}

// ---------------------------------------------------------------------------
// Launch.  Inputs: x, Wp, bp, emb, Wg, bg, We, k  (Wp/bp/bg/k provably unused)
// ---------------------------------------------------------------------------
extern "C" void kernel_launch(void* const* d_in, const int* in_sizes, int n_in,
                              void* d_out, int out_size) {
    const float* x   = (const float*)d_in[0];
    const float* emb = (const float*)d_in[3];
    const float* Wg  = (const float*)d_in[4];
    const float* We  = (const float*)d_in[6];
    float* out = (float*)d_out;

    cudaFuncSetAttribute(gemm_kernel,
                         cudaFuncAttributeMaxDynamicSharedMemorySize, GSMEM);

    gate_kernel<<<1, 32>>>(emb, Wg);
    prep_w<<<dim3(16, 16), dim3(32, 8)>>>(We);
    prep_x<<<BB * 2, 512>>>(x);
    gemm_kernel<<<(DD / CTA_M) * (BB * CC / CTA_N), 512, GSMEM>>>(out);
}

// round 5
// speedup vs baseline: 1.7115x; 1.0049x over previous
#include <cuda_runtime.h>
#include <cuda_bf16.h>
#include <cstdint>

// Problem constants
#define BB 512
#define SS 512
#define CC 32
#define DD 512
#define EE 8
#define EMBW 32

// ---------------------------------------------------------------------------
// Scratch (device globals — no allocation allowed)
// ---------------------------------------------------------------------------
__device__ __nv_bfloat16 g_Ahi[DD * SS];        // Wmix^T hi  [d][s] K-major
__device__ __nv_bfloat16 g_Alo[DD * SS];        // Wmix^T lo
__device__ __nv_bfloat16 g_Xhi[BB * CC * SS];   // xn hi [n=(b,v)][s] K-major
__device__ __nv_bfloat16 g_Xlo[BB * CC * SS];   // xn lo
__device__ float g_gw[2];
__device__ int   g_ge[2];

// ---------------------------------------------------------------------------
// helpers
// ---------------------------------------------------------------------------
__device__ __forceinline__ uint32_t smem_u32(const void* p) {
    uint32_t a;
    asm("{ .reg .u64 t; cvta.to.shared.u64 t, %1; cvt.u32.u64 %0, t; }"
        : "=r"(a) : "l"(p));
    return a;
}
__device__ __forceinline__ void cp_async16(uint32_t dst_smem, const void* src) {
    asm volatile("cp.async.cg.shared.global [%0], [%1], 16;"
                 :: "r"(dst_smem), "l"(src));
}
__device__ __forceinline__ void ldsm4(uint32_t* r, uint32_t addr) {
    asm volatile("ldmatrix.sync.aligned.m8n8.x4.shared.b16 {%0,%1,%2,%3}, [%4];"
                 : "=r"(r[0]), "=r"(r[1]), "=r"(r[2]), "=r"(r[3]) : "r"(addr));
}
__device__ __forceinline__ void mma_bf16(float* d, const uint32_t* a,
                                         uint32_t b0, uint32_t b1) {
    asm volatile(
        "mma.sync.aligned.m16n8k16.row.col.f32.bf16.bf16.f32 "
        "{%0,%1,%2,%3}, {%4,%5,%6,%7}, {%8,%9}, {%0,%1,%2,%3};"
        : "+f"(d[0]), "+f"(d[1]), "+f"(d[2]), "+f"(d[3])
        : "r"(a[0]), "r"(a[1]), "r"(a[2]), "r"(a[3]), "r"(b0), "r"(b1));
}

// ---------------------------------------------------------------------------
// K0: gate — logits separable => gates identical across batch.
// ---------------------------------------------------------------------------
__global__ void gate_kernel(const float* __restrict__ emb,
                            const float* __restrict__ Wg) {
    int lane = threadIdx.x;
    float t = -1e30f;
    if (lane < EE) {
        float s = 0.f;
        #pragma unroll
        for (int j = 0; j < EMBW; j++) s += emb[lane * EMBW + j] * Wg[DD + j];
        t = s;
    }
    float best = -1e30f, second = -1e30f;
    int be = 0, se = 0;
    #pragma unroll
    for (int e = 0; e < EE; e++) {
        float te = __shfl_sync(0xFFFFFFFFu, t, e);
        if (te > best)        { second = best; se = be; best = te; be = e; }
        else if (te > second) { second = te; se = e; }
    }
    if (lane == 0) {
        float e2 = expf(second - best);
        float inv = 1.0f / (1.0f + e2);
        g_gw[0] = inv;
        g_gw[1] = e2 * inv;
        g_ge[0] = be;
        g_ge[1] = se;
    }
}

// ---------------------------------------------------------------------------
// K1: prep_w — A[d][s] = g1*We[e1][s][d] + g2*We[e2][s][d], bf16 hi/lo split,
// K-major. 32x32 smem transpose tiles.
// ---------------------------------------------------------------------------
__global__ void prep_w(const float* __restrict__ We) {
    __shared__ float tile[32][33];
    int s0 = blockIdx.x * 32, d0 = blockIdx.y * 32;
    float g1 = g_gw[0], g2 = g_gw[1];
    const float* A1 = We + (size_t)g_ge[0] * SS * DD;
    const float* A2 = We + (size_t)g_ge[1] * SS * DD;
    int tx = threadIdx.x, ty = threadIdx.y;   // 32 x 8
    #pragma unroll
    for (int i = 0; i < 4; i++) {
        int s = s0 + ty + i * 8;
        tile[ty + i * 8][tx] =
            g1 * A1[(size_t)s * DD + d0 + tx] + g2 * A2[(size_t)s * DD + d0 + tx];
    }
    __syncthreads();
    #pragma unroll
    for (int i = 0; i < 4; i++) {
        int d = d0 + ty + i * 8;
        float v = tile[tx][ty + i * 8];
        __nv_bfloat16 h = __float2bfloat16(v);
        __nv_bfloat16 l = __float2bfloat16(v - __bfloat162float(h));
        g_Ahi[(size_t)d * SS + s0 + tx] = h;
        g_Alo[(size_t)d * SS + s0 + tx] = l;
    }
}

// ---------------------------------------------------------------------------
// K2: prep_x — fused exact median + subtract + bf16 hi/lo split + K-major
// transpose.  Block = (b, half of 32 channels), 16 warps, 1 warp/channel.
// ---------------------------------------------------------------------------
__device__ __forceinline__ unsigned f2ord(float f) {
    unsigned raw = __float_as_uint(f);
    return (raw & 0x80000000u) ? ~raw : (raw | 0x80000000u);
}
__device__ __forceinline__ float ord2f(unsigned u) {
    return (u & 0x80000000u) ? __uint_as_float(u ^ 0x80000000u)
                             : __uint_as_float(~u);
}

__global__ void __launch_bounds__(512) prep_x(const float* __restrict__ x) {
    __shared__ float sm[16 * 513];
    int b = blockIdx.x >> 1;
    int half = blockIdx.x & 1;
    const float4* xb4 = (const float4*)(x + (size_t)b * SS * CC + half * 16);

    for (int i = threadIdx.x; i < 512 * 4; i += 512) {
        int s = i >> 2, q = i & 3;
        float4 v = xb4[s * 8 + q];
        sm[(q * 4 + 0) * 513 + s] = v.x;
        sm[(q * 4 + 1) * 513 + s] = v.y;
        sm[(q * 4 + 2) * 513 + s] = v.z;
        sm[(q * 4 + 3) * 513 + s] = v.w;
    }
    __syncthreads();

    int w = threadIdx.x >> 5;
    int lane = threadIdx.x & 31;

    unsigned u[16];
    #pragma unroll
    for (int r = 0; r < 16; r++)
        u[r] = f2ord(sm[w * 513 + lane + 32 * r]);

    // radix select: order stat 255
    unsigned active = 0xFFFFu;
    int k = 255, na = 512;
    for (int bit = 31; bit >= 0; bit--) {
        unsigned m0 = 0;
        #pragma unroll
        for (int r = 0; r < 16; r++)
            m0 |= ((((u[r] >> bit) & 1u) ^ 1u) << r);
        m0 &= active;
        int tot0 = __reduce_add_sync(0xFFFFFFFFu, __popc(m0));
        if (k < tot0) { active = m0; na = tot0; }
        else          { k -= tot0; active &= ~m0; na -= tot0; }
        if (na == 1) break;
    }
    unsigned cand = 0;
    #pragma unroll
    for (int r = 0; r < 16; r++)
        if ((active >> r) & 1u) cand = u[r];
    unsigned v1 = __reduce_max_sync(0xFFFFFFFFu, cand);

    // order stat 256
    int le = 0;
    unsigned gtmin = 0xFFFFFFFFu;
    #pragma unroll
    for (int r = 0; r < 16; r++) {
        le += (u[r] <= v1) ? 1 : 0;
        if (u[r] > v1 && u[r] < gtmin) gtmin = u[r];
    }
    int totle = __reduce_add_sync(0xFFFFFFFFu, le);
    unsigned mn = __reduce_min_sync(0xFFFFFFFFu, gtmin);
    unsigned v2 = (totle >= 257) ? v1 : mn;
    float med = 0.5f * (ord2f(v1) + ord2f(v2));

    int c = half * 16 + w;
    __nv_bfloat16* dsth = g_Xhi + (size_t)(b * CC + c) * SS;
    __nv_bfloat16* dstl = g_Xlo + (size_t)(b * CC + c) * SS;
    #pragma unroll
    for (int r = 0; r < 8; r++) {
        int s = r * 64 + lane * 2;
        float a0 = sm[w * 513 + s]     - med;
        float a1 = sm[w * 513 + s + 1] - med;
        __nv_bfloat16 h0 = __float2bfloat16(a0);
        __nv_bfloat16 h1 = __float2bfloat16(a1);
        __nv_bfloat16 l0 = __float2bfloat16(a0 - __bfloat162float(h0));
        __nv_bfloat16 l1 = __float2bfloat16(a1 - __bfloat162float(h1));
        *reinterpret_cast<__nv_bfloat162*>(dsth + s) = __halves2bfloat162(h0, h1);
        *reinterpret_cast<__nv_bfloat162*>(dstl + s) = __halves2bfloat162(l0, l1);
    }
}

// ---------------------------------------------------------------------------
// K3: persistent mma.sync bf16x3 GEMM.
// Grid = 128 CTAs (4 m-tiles x 32 n-groups), 256 thr (8 warps), warp 32x64.
// Each CTA sweeps 4 n-tiles of 128 as one continuous 32-chunk stream with a
// 3-stage cp.async pipeline (no drain between n-tiles), 1 sync per chunk.
// ---------------------------------------------------------------------------
#define CTA_M 128
#define CTA_N 128
#define KC 64
#define NCH (SS / KC)            // 8 chunks per n-tile
#define NTPC 4                   // n-tiles per CTA
#define NIT (NTPC * NCH)         // 32 flat iterations
#define STG_BYTES 65536          // Ah 16K | Al 16K | Bh 16K | Bl 16K
#define OFF_AH 0
#define OFF_AL 16384
#define OFF_BH 32768
#define OFF_BL 49152
#define NSTG 3
#define GSMEM (NSTG * STG_BYTES) // 196608

__global__ void __launch_bounds__(256) gemm_kernel(float* __restrict__ out) {
    extern __shared__ char smem[];
    uint32_t sb = smem_u32(smem);
    int tid = threadIdx.x;
    int lane = tid & 31, wid = tid >> 5;
    int wm = wid & 3;            // 4 m-groups of 32
    int wn = wid >> 2;           // 2 n-groups of 64
    int m0 = (blockIdx.x & 3) * CTA_M;
    int ng = blockIdx.x >> 2;    // n-group: tiles ng*4 .. ng*4+3

    const char* gAh = (const char*)(g_Ahi + (size_t)m0 * SS);
    const char* gAl = (const char*)(g_Alo + (size_t)m0 * SS);
    const char* gBh = (const char*)g_Xhi;
    const char* gBl = (const char*)g_Xlo;

    auto ldchunk = [&](int stage, int it) {
        uint32_t tb = sb + stage * STG_BYTES;
        int u = it >> 3, ck = it & 7;
        size_t nrow0 = (size_t)(ng * NTPC + u) * CTA_N;
        size_t kb = (size_t)ck * (KC * 2);
        #pragma unroll
        for (int t = 0; t < 4; t++) {
            int idx = tid + t * 256;
            int r = idx >> 3, c = idx & 7;
            uint32_t so = (uint32_t)(r * 128 + ((c * 16) ^ ((r & 7) << 4)));
            size_t goA = (size_t)r * (SS * 2) + kb + c * 16;
            size_t goB = (nrow0 + r) * (SS * 2) + kb + c * 16;
            cp_async16(tb + OFF_AH + so, gAh + goA);
            cp_async16(tb + OFF_AL + so, gAl + goA);
            cp_async16(tb + OFF_BH + so, gBh + goB);
            cp_async16(tb + OFF_BL + so, gBl + goB);
        }
        asm volatile("cp.async.commit_group;" ::: "memory");
    };

    ldchunk(0, 0);
    ldchunk(1, 1);

    float acc[2][8][4];
    int r8 = lane & 7;
    int half8 = ((lane >> 3) & 1) * 8;
    int kh16 = (lane >> 4) * 16;

    for (int it = 0; it < NIT; it++) {
        // data for iter 'it' ready (outstanding: it+1 [+ possibly empty])
        asm volatile("cp.async.wait_group 1;" ::: "memory");
        __syncthreads();

        // prefetch iter it+2 into stage (it+2)%3 (freed by sync above)
        if (it + 2 < NIT) ldchunk((it + 2) % NSTG, it + 2);
        else asm volatile("cp.async.commit_group;" ::: "memory");

        if ((it & 7) == 0) {
            #pragma unroll
            for (int i = 0; i < 2; i++)
                #pragma unroll
                for (int j = 0; j < 8; j++)
                    #pragma unroll
                    for (int q = 0; q < 4; q++) acc[i][j][q] = 0.f;
        }

        uint32_t tb = sb + (it % NSTG) * STG_BYTES;
        #pragma unroll
        for (int ks = 0; ks < 4; ks++) {
            int kb0 = ks * 32 + kh16;
            uint32_t aH[2][4], aL[2][4];
            #pragma unroll
            for (int mb = 0; mb < 2; mb++) {
                int row = wm * 32 + mb * 16 + half8 + r8;
                uint32_t ad = (uint32_t)(row * 128 + (kb0 ^ ((row & 7) << 4)));
                ldsm4(aH[mb], tb + OFF_AH + ad);
                ldsm4(aL[mb], tb + OFF_AL + ad);
            }
            #pragma unroll
            for (int nb2 = 0; nb2 < 4; nb2++) {
                uint32_t bH[4], bL[4];
                int row = wn * 64 + nb2 * 16 + half8 + r8;
                uint32_t ad = (uint32_t)(row * 128 + (kb0 ^ ((row & 7) << 4)));
                ldsm4(bH, tb + OFF_BH + ad);
                ldsm4(bL, tb + OFF_BL + ad);
                #pragma unroll
                for (int mb = 0; mb < 2; mb++)
                    #pragma unroll
                    for (int s = 0; s < 2; s++) {
                        float* d = acc[mb][nb2 * 2 + s];
                        mma_bf16(d, aH[mb], bH[s], bH[s + 2]);
                        mma_bf16(d, aH[mb], bL[s], bL[s + 2]);
                        mma_bf16(d, aL[mb], bH[s], bH[s + 2]);
                    }
            }
        }

        if ((it & 7) == 7) {
            // store n-tile: warp covers n in [wn*64, wn*64+64) = 2 batch rows
            int u = it >> 3;
            int nbase = (ng * NTPC + u) * CTA_N + wn * 64;
            #pragma unroll
            for (int mb = 0; mb < 2; mb++) {
                int dr = m0 + wm * 32 + mb * 16 + (lane >> 2);
                #pragma unroll
                for (int nb8 = 0; nb8 < 8; nb8++) {
                    int bidx = (nbase >> 5) + (nb8 >> 2);
                    int v = (nb8 & 3) * 8 + 2 * (lane & 3);
                    float* ob = out + (size_t)bidx * DD * CC;
                    *(float2*)(ob + (size_t)dr * CC + v) =
                        make_float2(acc[mb][nb8][0], acc[mb][nb8][1]);
                    *(float2*)(ob + (size_t)(dr + 8) * CC + v) =
                        make_float2(acc[mb][nb8][2], acc[mb][nb8][3]);
                }
            }
        }
    }
}

// ---------------------------------------------------------------------------
// Launch.  Inputs: x, Wp, bp, emb, Wg, bg, We, k  (Wp/bp/bg/k provably unused)
// ---------------------------------------------------------------------------
extern "C" void kernel_launch(void* const* d_in, const int* in_sizes, int n_in,
                              void* d_out, int out_size) {
    const float* x   = (const float*)d_in[0];
    const float* emb = (const float*)d_in[3];
    const float* Wg  = (const float*)d_in[4];
    const float* We  = (const float*)d_in[6];
    float* out = (float*)d_out;

    cudaFuncSetAttribute(gemm_kernel,
                         cudaFuncAttributeMaxDynamicSharedMemorySize, GSMEM);

    gate_kernel<<<1, 32>>>(emb, Wg);
    prep_w<<<dim3(16, 16), dim3(32, 8)>>>(We);
    prep_x<<<BB * 2, 512>>>(x);
    gemm_kernel<<<128, 256, GSMEM>>>(out);
}

// round 6
// speedup vs baseline: 1.7306x; 1.0112x over previous
#include <cuda_runtime.h>
#include <cuda_bf16.h>
#include <cstdint>

// Problem constants
#define BB 512
#define SS 512
#define CC 32
#define DD 512
#define EE 8
#define EMBW 32

// ---------------------------------------------------------------------------
// Scratch (device globals — no allocation allowed)
// ---------------------------------------------------------------------------
__device__ __nv_bfloat16 g_Ahi[DD * SS];        // Wmix^T hi  [d][s] K-major
__device__ __nv_bfloat16 g_Alo[DD * SS];        // Wmix^T lo
__device__ __nv_bfloat16 g_Xhi[BB * CC * SS];   // xn hi [n=(b,v)][s] K-major
__device__ __nv_bfloat16 g_Xlo[BB * CC * SS];   // xn lo
__device__ float g_gw[2];
__device__ int   g_ge[2];

// ---------------------------------------------------------------------------
// helpers
// ---------------------------------------------------------------------------
__device__ __forceinline__ uint32_t smem_u32(const void* p) {
    uint32_t a;
    asm("{ .reg .u64 t; cvta.to.shared.u64 t, %1; cvt.u32.u64 %0, t; }"
        : "=r"(a) : "l"(p));
    return a;
}
__device__ __forceinline__ void cp_async16(uint32_t dst_smem, const void* src) {
    asm volatile("cp.async.cg.shared.global [%0], [%1], 16;"
                 :: "r"(dst_smem), "l"(src));
}
__device__ __forceinline__ void ldsm4(uint32_t* r, uint32_t addr) {
    asm volatile("ldmatrix.sync.aligned.m8n8.x4.shared.b16 {%0,%1,%2,%3}, [%4];"
                 : "=r"(r[0]), "=r"(r[1]), "=r"(r[2]), "=r"(r[3]) : "r"(addr));
}
__device__ __forceinline__ void mma_bf16(float* d, const uint32_t* a,
                                         uint32_t b0, uint32_t b1) {
    asm volatile(
        "mma.sync.aligned.m16n8k16.row.col.f32.bf16.bf16.f32 "
        "{%0,%1,%2,%3}, {%4,%5,%6,%7}, {%8,%9}, {%0,%1,%2,%3};"
        : "+f"(d[0]), "+f"(d[1]), "+f"(d[2]), "+f"(d[3])
        : "r"(a[0]), "r"(a[1]), "r"(a[2]), "r"(a[3]), "r"(b0), "r"(b1));
}

// ---------------------------------------------------------------------------
// K0: gate — logits separable => gates identical across batch.
// ---------------------------------------------------------------------------
__global__ void gate_kernel(const float* __restrict__ emb,
                            const float* __restrict__ Wg) {
    int lane = threadIdx.x;
    float t = -1e30f;
    if (lane < EE) {
        float s = 0.f;
        #pragma unroll
        for (int j = 0; j < EMBW; j++) s += emb[lane * EMBW + j] * Wg[DD + j];
        t = s;
    }
    float best = -1e30f, second = -1e30f;
    int be = 0, se = 0;
    #pragma unroll
    for (int e = 0; e < EE; e++) {
        float te = __shfl_sync(0xFFFFFFFFu, t, e);
        if (te > best)        { second = best; se = be; best = te; be = e; }
        else if (te > second) { second = te; se = e; }
    }
    if (lane == 0) {
        float e2 = expf(second - best);
        float inv = 1.0f / (1.0f + e2);
        g_gw[0] = inv;
        g_gw[1] = e2 * inv;
        g_ge[0] = be;
        g_ge[1] = se;
    }
}

// ---------------------------------------------------------------------------
// K1: prep_w — A[d][s] = g1*We[e1][s][d] + g2*We[e2][s][d], bf16 hi/lo split,
// K-major. 32x32 smem transpose tiles.
// ---------------------------------------------------------------------------
__global__ void prep_w(const float* __restrict__ We) {
    __shared__ float tile[32][33];
    int s0 = blockIdx.x * 32, d0 = blockIdx.y * 32;
    float g1 = g_gw[0], g2 = g_gw[1];
    const float* A1 = We + (size_t)g_ge[0] * SS * DD;
    const float* A2 = We + (size_t)g_ge[1] * SS * DD;
    int tx = threadIdx.x, ty = threadIdx.y;   // 32 x 8
    #pragma unroll
    for (int i = 0; i < 4; i++) {
        int s = s0 + ty + i * 8;
        tile[ty + i * 8][tx] =
            g1 * A1[(size_t)s * DD + d0 + tx] + g2 * A2[(size_t)s * DD + d0 + tx];
    }
    __syncthreads();
    #pragma unroll
    for (int i = 0; i < 4; i++) {
        int d = d0 + ty + i * 8;
        float v = tile[tx][ty + i * 8];
        __nv_bfloat16 h = __float2bfloat16(v);
        __nv_bfloat16 l = __float2bfloat16(v - __bfloat162float(h));
        g_Ahi[(size_t)d * SS + s0 + tx] = h;
        g_Alo[(size_t)d * SS + s0 + tx] = l;
    }
}

// ---------------------------------------------------------------------------
// K2: prep_x — fused exact median + subtract + bf16 hi/lo split + K-major
// transpose.  Block = (b, half of 32 channels), 16 warps, 1 warp/channel.
// ---------------------------------------------------------------------------
__device__ __forceinline__ unsigned f2ord(float f) {
    unsigned raw = __float_as_uint(f);
    return (raw & 0x80000000u) ? ~raw : (raw | 0x80000000u);
}
__device__ __forceinline__ float ord2f(unsigned u) {
    return (u & 0x80000000u) ? __uint_as_float(u ^ 0x80000000u)
                             : __uint_as_float(~u);
}

__global__ void __launch_bounds__(512) prep_x(const float* __restrict__ x) {
    __shared__ float sm[16 * 513];
    int b = blockIdx.x >> 1;
    int half = blockIdx.x & 1;
    const float4* xb4 = (const float4*)(x + (size_t)b * SS * CC + half * 16);

    for (int i = threadIdx.x; i < 512 * 4; i += 512) {
        int s = i >> 2, q = i & 3;
        float4 v = xb4[s * 8 + q];
        sm[(q * 4 + 0) * 513 + s] = v.x;
        sm[(q * 4 + 1) * 513 + s] = v.y;
        sm[(q * 4 + 2) * 513 + s] = v.z;
        sm[(q * 4 + 3) * 513 + s] = v.w;
    }
    __syncthreads();

    int w = threadIdx.x >> 5;
    int lane = threadIdx.x & 31;

    unsigned u[16];
    #pragma unroll
    for (int r = 0; r < 16; r++)
        u[r] = f2ord(sm[w * 513 + lane + 32 * r]);

    // radix select: order stat 255
    unsigned active = 0xFFFFu;
    int k = 255, na = 512;
    for (int bit = 31; bit >= 0; bit--) {
        unsigned m0 = 0;
        #pragma unroll
        for (int r = 0; r < 16; r++)
            m0 |= ((((u[r] >> bit) & 1u) ^ 1u) << r);
        m0 &= active;
        int tot0 = __reduce_add_sync(0xFFFFFFFFu, __popc(m0));
        if (k < tot0) { active = m0; na = tot0; }
        else          { k -= tot0; active &= ~m0; na -= tot0; }
        if (na == 1) break;
    }
    unsigned cand = 0;
    #pragma unroll
    for (int r = 0; r < 16; r++)
        if ((active >> r) & 1u) cand = u[r];
    unsigned v1 = __reduce_max_sync(0xFFFFFFFFu, cand);

    // order stat 256
    int le = 0;
    unsigned gtmin = 0xFFFFFFFFu;
    #pragma unroll
    for (int r = 0; r < 16; r++) {
        le += (u[r] <= v1) ? 1 : 0;
        if (u[r] > v1 && u[r] < gtmin) gtmin = u[r];
    }
    int totle = __reduce_add_sync(0xFFFFFFFFu, le);
    unsigned mn = __reduce_min_sync(0xFFFFFFFFu, gtmin);
    unsigned v2 = (totle >= 257) ? v1 : mn;
    float med = 0.5f * (ord2f(v1) + ord2f(v2));

    int c = half * 16 + w;
    __nv_bfloat16* dsth = g_Xhi + (size_t)(b * CC + c) * SS;
    __nv_bfloat16* dstl = g_Xlo + (size_t)(b * CC + c) * SS;
    #pragma unroll
    for (int r = 0; r < 8; r++) {
        int s = r * 64 + lane * 2;
        float a0 = sm[w * 513 + s]     - med;
        float a1 = sm[w * 513 + s + 1] - med;
        __nv_bfloat16 h0 = __float2bfloat16(a0);
        __nv_bfloat16 h1 = __float2bfloat16(a1);
        __nv_bfloat16 l0 = __float2bfloat16(a0 - __bfloat162float(h0));
        __nv_bfloat16 l1 = __float2bfloat16(a1 - __bfloat162float(h1));
        *reinterpret_cast<__nv_bfloat162*>(dsth + s) = __halves2bfloat162(h0, h1);
        *reinterpret_cast<__nv_bfloat162*>(dstl + s) = __halves2bfloat162(l0, l1);
    }
}

// ---------------------------------------------------------------------------
// K3: persistent mma.sync bf16x3 GEMM, pass-major MMA issue order.
// Grid = 128 CTAs (4 m-tiles x 32 n-groups), 256 thr (8 warps), warp 32x64.
// All fragments for a k-slice are hoisted; the 48 MMAs issue as 3 passes of
// 16 independent accumulators, so same-acc MMAs are 16 instructions apart.
// ---------------------------------------------------------------------------
#define CTA_M 128
#define CTA_N 128
#define KC 64
#define NCH (SS / KC)            // 8 chunks per n-tile
#define NTPC 4                   // n-tiles per CTA
#define NIT (NTPC * NCH)         // 32 flat iterations
#define STG_BYTES 65536          // Ah 16K | Al 16K | Bh 16K | Bl 16K
#define OFF_AH 0
#define OFF_AL 16384
#define OFF_BH 32768
#define OFF_BL 49152
#define NSTG 3
#define GSMEM (NSTG * STG_BYTES) // 196608

__global__ void __launch_bounds__(256) gemm_kernel(float* __restrict__ out) {
    extern __shared__ char smem[];
    uint32_t sb = smem_u32(smem);
    int tid = threadIdx.x;
    int lane = tid & 31, wid = tid >> 5;
    int wm = wid & 3;            // 4 m-groups of 32
    int wn = wid >> 2;           // 2 n-groups of 64
    int m0 = (blockIdx.x & 3) * CTA_M;
    int ng = blockIdx.x >> 2;    // n-group: tiles ng*4 .. ng*4+3

    const char* gAh = (const char*)(g_Ahi + (size_t)m0 * SS);
    const char* gAl = (const char*)(g_Alo + (size_t)m0 * SS);
    const char* gBh = (const char*)g_Xhi;
    const char* gBl = (const char*)g_Xlo;

    auto ldchunk = [&](int stage, int it) {
        uint32_t tb = sb + stage * STG_BYTES;
        int u = it >> 3, ck = it & 7;
        size_t nrow0 = (size_t)(ng * NTPC + u) * CTA_N;
        size_t kb = (size_t)ck * (KC * 2);
        #pragma unroll
        for (int t = 0; t < 4; t++) {
            int idx = tid + t * 256;
            int r = idx >> 3, c = idx & 7;
            uint32_t so = (uint32_t)(r * 128 + ((c * 16) ^ ((r & 7) << 4)));
            size_t goA = (size_t)r * (SS * 2) + kb + c * 16;
            size_t goB = (nrow0 + r) * (SS * 2) + kb + c * 16;
            cp_async16(tb + OFF_AH + so, gAh + goA);
            cp_async16(tb + OFF_AL + so, gAl + goA);
            cp_async16(tb + OFF_BH + so, gBh + goB);
            cp_async16(tb + OFF_BL + so, gBl + goB);
        }
        asm volatile("cp.async.commit_group;" ::: "memory");
    };

    ldchunk(0, 0);
    ldchunk(1, 1);

    float acc[2][8][4];
    int r8 = lane & 7;
    int half8 = ((lane >> 3) & 1) * 8;
    int kh16 = (lane >> 4) * 16;

    for (int it = 0; it < NIT; it++) {
        asm volatile("cp.async.wait_group 1;" ::: "memory");
        __syncthreads();

        if (it + 2 < NIT) ldchunk((it + 2) % NSTG, it + 2);
        else asm volatile("cp.async.commit_group;" ::: "memory");

        if ((it & 7) == 0) {
            #pragma unroll
            for (int i = 0; i < 2; i++)
                #pragma unroll
                for (int j = 0; j < 8; j++)
                    #pragma unroll
                    for (int q = 0; q < 4; q++) acc[i][j][q] = 0.f;
        }

        uint32_t tb = sb + (it % NSTG) * STG_BYTES;
        #pragma unroll
        for (int ks = 0; ks < 4; ks++) {
            int kb0 = ks * 32 + kh16;
            uint32_t aH[2][4], aL[2][4], bH[4][4], bL[4][4];
            #pragma unroll
            for (int mb = 0; mb < 2; mb++) {
                int row = wm * 32 + mb * 16 + half8 + r8;
                uint32_t ad = (uint32_t)(row * 128 + (kb0 ^ ((row & 7) << 4)));
                ldsm4(aH[mb], tb + OFF_AH + ad);
                ldsm4(aL[mb], tb + OFF_AL + ad);
            }
            #pragma unroll
            for (int nb2 = 0; nb2 < 4; nb2++) {
                int row = wn * 64 + nb2 * 16 + half8 + r8;
                uint32_t ad = (uint32_t)(row * 128 + (kb0 ^ ((row & 7) << 4)));
                ldsm4(bH[nb2], tb + OFF_BH + ad);
                ldsm4(bL[nb2], tb + OFF_BL + ad);
            }
            // pass-major issue: 16 independent accumulators per pass
            #pragma unroll
            for (int mb = 0; mb < 2; mb++)
                #pragma unroll
                for (int nb2 = 0; nb2 < 4; nb2++)
                    #pragma unroll
                    for (int s = 0; s < 2; s++)
                        mma_bf16(acc[mb][nb2 * 2 + s], aH[mb],
                                 bH[nb2][s], bH[nb2][s + 2]);
            #pragma unroll
            for (int mb = 0; mb < 2; mb++)
                #pragma unroll
                for (int nb2 = 0; nb2 < 4; nb2++)
                    #pragma unroll
                    for (int s = 0; s < 2; s++)
                        mma_bf16(acc[mb][nb2 * 2 + s], aH[mb],
                                 bL[nb2][s], bL[nb2][s + 2]);
            #pragma unroll
            for (int mb = 0; mb < 2; mb++)
                #pragma unroll
                for (int nb2 = 0; nb2 < 4; nb2++)
                    #pragma unroll
                    for (int s = 0; s < 2; s++)
                        mma_bf16(acc[mb][nb2 * 2 + s], aL[mb],
                                 bH[nb2][s], bH[nb2][s + 2]);
        }

        if ((it & 7) == 7) {
            int u = it >> 3;
            int nbase = (ng * NTPC + u) * CTA_N + wn * 64;
            #pragma unroll
            for (int mb = 0; mb < 2; mb++) {
                int dr = m0 + wm * 32 + mb * 16 + (lane >> 2);
                #pragma unroll
                for (int nb8 = 0; nb8 < 8; nb8++) {
                    int bidx = (nbase >> 5) + (nb8 >> 2);
                    int v = (nb8 & 3) * 8 + 2 * (lane & 3);
                    float* ob = out + (size_t)bidx * DD * CC;
                    *(float2*)(ob + (size_t)dr * CC + v) =
                        make_float2(acc[mb][nb8][0], acc[mb][nb8][1]);
                    *(float2*)(ob + (size_t)(dr + 8) * CC + v) =
                        make_float2(acc[mb][nb8][2], acc[mb][nb8][3]);
                }
            }
        }
    }
}

// ---------------------------------------------------------------------------
// Launch.  Inputs: x, Wp, bp, emb, Wg, bg, We, k  (Wp/bp/bg/k provably unused)
// ---------------------------------------------------------------------------
extern "C" void kernel_launch(void* const* d_in, const int* in_sizes, int n_in,
                              void* d_out, int out_size) {
    const float* x   = (const float*)d_in[0];
    const float* emb = (const float*)d_in[3];
    const float* Wg  = (const float*)d_in[4];
    const float* We  = (const float*)d_in[6];
    float* out = (float*)d_out;

    cudaFuncSetAttribute(gemm_kernel,
                         cudaFuncAttributeMaxDynamicSharedMemorySize, GSMEM);

    gate_kernel<<<1, 32>>>(emb, Wg);
    prep_w<<<dim3(16, 16), dim3(32, 8)>>>(We);
    prep_x<<<BB * 2, 512>>>(x);
    gemm_kernel<<<128, 256, GSMEM>>>(out);
}

// round 7
// speedup vs baseline: 2.9114x; 1.6823x over previous
#include <cuda_runtime.h>
#include <cuda_fp16.h>
#include <cstdint>

// Problem constants
#define BB 512
#define SS 512
#define CC 32
#define DD 512
#define EE 8
#define EMBW 32

// ---------------------------------------------------------------------------
// Scratch (device globals — no allocation allowed)
// ---------------------------------------------------------------------------
__device__ __half g_Ah[DD * SS];        // Wmix^T fp16  [d][s] K-major
__device__ __half g_Xh[BB * CC * SS];   // xn fp16 [n=(b,v)][s] K-major
__device__ float g_gw[2];
__device__ int   g_ge[2];

// ---------------------------------------------------------------------------
// helpers
// ---------------------------------------------------------------------------
__device__ __forceinline__ uint32_t smem_u32(const void* p) {
    uint32_t a;
    asm("{ .reg .u64 t; cvta.to.shared.u64 t, %1; cvt.u32.u64 %0, t; }"
        : "=r"(a) : "l"(p));
    return a;
}
__device__ __forceinline__ void cp_async16(uint32_t dst_smem, const void* src) {
    asm volatile("cp.async.cg.shared.global [%0], [%1], 16;"
                 :: "r"(dst_smem), "l"(src));
}
__device__ __forceinline__ void ldsm4(uint32_t* r, uint32_t addr) {
    asm volatile("ldmatrix.sync.aligned.m8n8.x4.shared.b16 {%0,%1,%2,%3}, [%4];"
                 : "=r"(r[0]), "=r"(r[1]), "=r"(r[2]), "=r"(r[3]) : "r"(addr));
}
__device__ __forceinline__ void mma_fp16(float* d, const uint32_t* a,
                                         uint32_t b0, uint32_t b1) {
    asm volatile(
        "mma.sync.aligned.m16n8k16.row.col.f32.f16.f16.f32 "
        "{%0,%1,%2,%3}, {%4,%5,%6,%7}, {%8,%9}, {%0,%1,%2,%3};"
        : "+f"(d[0]), "+f"(d[1]), "+f"(d[2]), "+f"(d[3])
        : "r"(a[0]), "r"(a[1]), "r"(a[2]), "r"(a[3]), "r"(b0), "r"(b1));
}

// ---------------------------------------------------------------------------
// K0: gate — logits separable => gates identical across batch.
// ---------------------------------------------------------------------------
__global__ void gate_kernel(const float* __restrict__ emb,
                            const float* __restrict__ Wg) {
    int lane = threadIdx.x;
    float t = -1e30f;
    if (lane < EE) {
        float s = 0.f;
        #pragma unroll
        for (int j = 0; j < EMBW; j++) s += emb[lane * EMBW + j] * Wg[DD + j];
        t = s;
    }
    float best = -1e30f, second = -1e30f;
    int be = 0, se = 0;
    #pragma unroll
    for (int e = 0; e < EE; e++) {
        float te = __shfl_sync(0xFFFFFFFFu, t, e);
        if (te > best)        { second = best; se = be; best = te; be = e; }
        else if (te > second) { second = te; se = e; }
    }
    if (lane == 0) {
        float e2 = expf(second - best);
        float inv = 1.0f / (1.0f + e2);
        g_gw[0] = inv;
        g_gw[1] = e2 * inv;
        g_ge[0] = be;
        g_ge[1] = se;
    }
}

// ---------------------------------------------------------------------------
// K1: prep_w — A[d][s] = g1*We[e1][s][d] + g2*We[e2][s][d], fp16, K-major.
// 32x32 smem transpose tiles.
// ---------------------------------------------------------------------------
__global__ void prep_w(const float* __restrict__ We) {
    __shared__ float tile[32][33];
    int s0 = blockIdx.x * 32, d0 = blockIdx.y * 32;
    float g1 = g_gw[0], g2 = g_gw[1];
    const float* A1 = We + (size_t)g_ge[0] * SS * DD;
    const float* A2 = We + (size_t)g_ge[1] * SS * DD;
    int tx = threadIdx.x, ty = threadIdx.y;   // 32 x 8
    #pragma unroll
    for (int i = 0; i < 4; i++) {
        int s = s0 + ty + i * 8;
        tile[ty + i * 8][tx] =
            g1 * A1[(size_t)s * DD + d0 + tx] + g2 * A2[(size_t)s * DD + d0 + tx];
    }
    __syncthreads();
    #pragma unroll
    for (int i = 0; i < 4; i++) {
        int d = d0 + ty + i * 8;
        g_Ah[(size_t)d * SS + s0 + tx] = __float2half_rn(tile[tx][ty + i * 8]);
    }
}

// ---------------------------------------------------------------------------
// K2: prep_x — fused exact median + subtract + fp16 convert + K-major
// transpose.  Block = (b, half of 32 channels), 16 warps, 1 warp/channel.
// ---------------------------------------------------------------------------
__device__ __forceinline__ unsigned f2ord(float f) {
    unsigned raw = __float_as_uint(f);
    return (raw & 0x80000000u) ? ~raw : (raw | 0x80000000u);
}
__device__ __forceinline__ float ord2f(unsigned u) {
    return (u & 0x80000000u) ? __uint_as_float(u ^ 0x80000000u)
                             : __uint_as_float(~u);
}

__global__ void __launch_bounds__(512) prep_x(const float* __restrict__ x) {
    __shared__ float sm[16 * 513];
    int b = blockIdx.x >> 1;
    int half = blockIdx.x & 1;
    const float4* xb4 = (const float4*)(x + (size_t)b * SS * CC + half * 16);

    for (int i = threadIdx.x; i < 512 * 4; i += 512) {
        int s = i >> 2, q = i & 3;
        float4 v = xb4[s * 8 + q];
        sm[(q * 4 + 0) * 513 + s] = v.x;
        sm[(q * 4 + 1) * 513 + s] = v.y;
        sm[(q * 4 + 2) * 513 + s] = v.z;
        sm[(q * 4 + 3) * 513 + s] = v.w;
    }
    __syncthreads();

    int w = threadIdx.x >> 5;
    int lane = threadIdx.x & 31;

    unsigned u[16];
    #pragma unroll
    for (int r = 0; r < 16; r++)
        u[r] = f2ord(sm[w * 513 + lane + 32 * r]);

    // radix select: order stat 255
    unsigned active = 0xFFFFu;
    int k = 255, na = 512;
    for (int bit = 31; bit >= 0; bit--) {
        unsigned m0 = 0;
        #pragma unroll
        for (int r = 0; r < 16; r++)
            m0 |= ((((u[r] >> bit) & 1u) ^ 1u) << r);
        m0 &= active;
        int tot0 = __reduce_add_sync(0xFFFFFFFFu, __popc(m0));
        if (k < tot0) { active = m0; na = tot0; }
        else          { k -= tot0; active &= ~m0; na -= tot0; }
        if (na == 1) break;
    }
    unsigned cand = 0;
    #pragma unroll
    for (int r = 0; r < 16; r++)
        if ((active >> r) & 1u) cand = u[r];
    unsigned v1 = __reduce_max_sync(0xFFFFFFFFu, cand);

    // order stat 256
    int le = 0;
    unsigned gtmin = 0xFFFFFFFFu;
    #pragma unroll
    for (int r = 0; r < 16; r++) {
        le += (u[r] <= v1) ? 1 : 0;
        if (u[r] > v1 && u[r] < gtmin) gtmin = u[r];
    }
    int totle = __reduce_add_sync(0xFFFFFFFFu, le);
    unsigned mn = __reduce_min_sync(0xFFFFFFFFu, gtmin);
    unsigned v2 = (totle >= 257) ? v1 : mn;
    float med = 0.5f * (ord2f(v1) + ord2f(v2));

    int c = half * 16 + w;
    __half* dsth = g_Xh + (size_t)(b * CC + c) * SS;
    #pragma unroll
    for (int r = 0; r < 8; r++) {
        int s = r * 64 + lane * 2;
        float a0 = sm[w * 513 + s]     - med;
        float a1 = sm[w * 513 + s + 1] - med;
        *reinterpret_cast<__half2*>(dsth + s) = __floats2half2_rn(a0, a1);
    }
}

// ---------------------------------------------------------------------------
// K3: persistent single-pass fp16 mma.sync GEMM (fp32 accumulate).
// Grid = 128 CTAs (4 m-tiles x 32 n-groups), 256 thr (8 warps), warp 32x64.
// KC=64, 4-stage cp.async pipeline, prefetch distance 3, continuous stream
// across the CTA's 4 n-tiles.
// ---------------------------------------------------------------------------
#define CTA_M 128
#define CTA_N 128
#define KC 64
#define NCH (SS / KC)            // 8 chunks per n-tile
#define NTPC 4                   // n-tiles per CTA
#define NIT (NTPC * NCH)         // 32 flat iterations
#define STG_BYTES 32768          // Ah 16K | Bh 16K
#define OFF_AH 0
#define OFF_BH 16384
#define NSTG 4
#define GSMEM (NSTG * STG_BYTES) // 131072

__global__ void __launch_bounds__(256) gemm_kernel(float* __restrict__ out) {
    extern __shared__ char smem[];
    uint32_t sb = smem_u32(smem);
    int tid = threadIdx.x;
    int lane = tid & 31, wid = tid >> 5;
    int wm = wid & 3;            // 4 m-groups of 32
    int wn = wid >> 2;           // 2 n-groups of 64
    int m0 = (blockIdx.x & 3) * CTA_M;
    int ng = blockIdx.x >> 2;    // n-group: tiles ng*4 .. ng*4+3

    const char* gA = (const char*)(g_Ah + (size_t)m0 * SS);
    const char* gB = (const char*)g_Xh;

    auto ldchunk = [&](int stage, int it) {
        uint32_t tb = sb + stage * STG_BYTES;
        int u = it >> 3, ck = it & 7;
        size_t nrow0 = (size_t)(ng * NTPC + u) * CTA_N;
        size_t kb = (size_t)ck * (KC * 2);
        #pragma unroll
        for (int t = 0; t < 4; t++) {
            int idx = tid + t * 256;
            int r = idx >> 3, c = idx & 7;
            uint32_t so = (uint32_t)(r * 128 + ((c * 16) ^ ((r & 7) << 4)));
            size_t goA = (size_t)r * (SS * 2) + kb + c * 16;
            size_t goB = (nrow0 + r) * (SS * 2) + kb + c * 16;
            cp_async16(tb + OFF_AH + so, gA + goA);
            cp_async16(tb + OFF_BH + so, gB + goB);
        }
        asm volatile("cp.async.commit_group;" ::: "memory");
    };

    ldchunk(0, 0);
    ldchunk(1, 1);
    ldchunk(2, 2);

    float acc[2][8][4];
    int r8 = lane & 7;
    int half8 = ((lane >> 3) & 1) * 8;
    int kh16 = (lane >> 4) * 16;

    for (int it = 0; it < NIT; it++) {
        // group for 'it' complete; it+1, it+2 may remain outstanding
        asm volatile("cp.async.wait_group 2;" ::: "memory");
        __syncthreads();

        // stage (it+3)%4 == (it-1)%4 is free after the sync above
        if (it + 3 < NIT) ldchunk((it + 3) % NSTG, it + 3);
        else asm volatile("cp.async.commit_group;" ::: "memory");

        if ((it & 7) == 0) {
            #pragma unroll
            for (int i = 0; i < 2; i++)
                #pragma unroll
                for (int j = 0; j < 8; j++)
                    #pragma unroll
                    for (int q = 0; q < 4; q++) acc[i][j][q] = 0.f;
        }

        uint32_t tb = sb + (it % NSTG) * STG_BYTES;
        #pragma unroll
        for (int ks = 0; ks < 4; ks++) {
            int kb0 = ks * 32 + kh16;
            uint32_t a[2][4], bfr[4][4];
            #pragma unroll
            for (int mb = 0; mb < 2; mb++) {
                int row = wm * 32 + mb * 16 + half8 + r8;
                uint32_t ad = (uint32_t)(row * 128 + (kb0 ^ ((row & 7) << 4)));
                ldsm4(a[mb], tb + OFF_AH + ad);
            }
            #pragma unroll
            for (int nb2 = 0; nb2 < 4; nb2++) {
                int row = wn * 64 + nb2 * 16 + half8 + r8;
                uint32_t ad = (uint32_t)(row * 128 + (kb0 ^ ((row & 7) << 4)));
                ldsm4(bfr[nb2], tb + OFF_BH + ad);
            }
            #pragma unroll
            for (int mb = 0; mb < 2; mb++)
                #pragma unroll
                for (int nb2 = 0; nb2 < 4; nb2++)
                    #pragma unroll
                    for (int s = 0; s < 2; s++)
                        mma_fp16(acc[mb][nb2 * 2 + s], a[mb],
                                 bfr[nb2][s], bfr[nb2][s + 2]);
        }

        if ((it & 7) == 7) {
            int u = it >> 3;
            int nbase = (ng * NTPC + u) * CTA_N + wn * 64;
            #pragma unroll
            for (int mb = 0; mb < 2; mb++) {
                int dr = m0 + wm * 32 + mb * 16 + (lane >> 2);
                #pragma unroll
                for (int nb8 = 0; nb8 < 8; nb8++) {
                    int bidx = (nbase >> 5) + (nb8 >> 2);
                    int v = (nb8 & 3) * 8 + 2 * (lane & 3);
                    float* ob = out + (size_t)bidx * DD * CC;
                    *(float2*)(ob + (size_t)dr * CC + v) =
                        make_float2(acc[mb][nb8][0], acc[mb][nb8][1]);
                    *(float2*)(ob + (size_t)(dr + 8) * CC + v) =
                        make_float2(acc[mb][nb8][2], acc[mb][nb8][3]);
                }
            }
        }
    }
}

// ---------------------------------------------------------------------------
// Launch.  Inputs: x, Wp, bp, emb, Wg, bg, We, k  (Wp/bp/bg/k provably unused)
// ---------------------------------------------------------------------------
extern "C" void kernel_launch(void* const* d_in, const int* in_sizes, int n_in,
                              void* d_out, int out_size) {
    const float* x   = (const float*)d_in[0];
    const float* emb = (const float*)d_in[3];
    const float* Wg  = (const float*)d_in[4];
    const float* We  = (const float*)d_in[6];
    float* out = (float*)d_out;

    cudaFuncSetAttribute(gemm_kernel,
                         cudaFuncAttributeMaxDynamicSharedMemorySize, GSMEM);

    gate_kernel<<<1, 32>>>(emb, Wg);
    prep_w<<<dim3(16, 16), dim3(32, 8)>>>(We);
    prep_x<<<BB * 2, 512>>>(x);
    gemm_kernel<<<128, 256, GSMEM>>>(out);
}